// round 5
// baseline (speedup 1.0000x reference)
#include <cuda_runtime.h>
#include <cuda_bf16.h>
#include <cstdint>

// Problem constants
#define BB 8
#define TT 1024
#define HH 1024
#define MM (BB * TT)      // 8192 rows
#define LN_EPS 1e-5f

// HMMA GEMM tiling: CTA 256x128, 8 warps of 64x64
#define BM 256
#define BN 128
#define BKE 32                 // bf16 K elems per stage
#define NSTAGE 3
#define STAGE_BYTES 49152      // A(hi+lo): 2x16KB, B(hi+lo): 2x8KB
#define GEMM_SMEM (NSTAGE * STAGE_BYTES)   // 147456

// msg scan
#define SC_TC 128
#define RING_MAX 40

// ---------------------------------------------------------------------------
// Scratch (device globals — allocation-free rule)
// ---------------------------------------------------------------------------
__device__ __nv_bfloat16 g_xh[MM * HH], g_xl[MM * HH];
__device__ __nv_bfloat16 g_mh[MM * HH], g_ml[MM * HH];
__device__ __nv_bfloat16 g_rh[MM * HH], g_rl[MM * HH];
__device__ __nv_bfloat16 g_wst_h[HH * HH], g_wst_l[HH * HH];   // W_self^T [n][k]
__device__ __nv_bfloat16 g_wmt_h[HH * HH], g_wmt_l[HH * HH];   // W_msg^T
__device__ __nv_bfloat16 g_wot_h[HH * HH], g_wot_l[HH * HH];   // W_out^T
__device__ float g_z[MM * HH];

// ---------------------------------------------------------------------------
// PTX helpers (baseline ISA — compiles at compute_103)
// ---------------------------------------------------------------------------
__device__ __forceinline__ uint32_t smem_u32(const void* p) {
    uint32_t a;
    asm("{ .reg .u64 t; cvta.to.shared.u64 t, %1; cvt.u32.u64 %0, t; }"
        : "=r"(a) : "l"(p));
    return a;
}
__device__ __forceinline__ void cp16(uint32_t dst, const void* src) {
    asm volatile("cp.async.cg.shared.global [%0], [%1], 16;" :: "r"(dst), "l"(src));
}
__device__ __forceinline__ void ldsm4(uint32_t* r, uint32_t a) {
    asm volatile("ldmatrix.sync.aligned.m8n8.x4.shared.b16 {%0,%1,%2,%3}, [%4];"
        : "=r"(r[0]), "=r"(r[1]), "=r"(r[2]), "=r"(r[3]) : "r"(a));
}
__device__ __forceinline__ void mma16816(float* c, const uint32_t* a,
                                         uint32_t b0, uint32_t b1) {
    asm volatile(
        "mma.sync.aligned.m16n8k16.row.col.f32.bf16.bf16.f32 "
        "{%0,%1,%2,%3}, {%4,%5,%6,%7}, {%8,%9}, {%0,%1,%2,%3};"
        : "+f"(c[0]), "+f"(c[1]), "+f"(c[2]), "+f"(c[3])
        : "r"(a[0]), "r"(a[1]), "r"(a[2]), "r"(a[3]), "r"(b0), "r"(b1));
}

// Tile rows are 64B (32 bf16); 16B chunk index XOR-swizzled with (row>>1)&3.
__device__ __forceinline__ uint32_t ldsm_addr(uint32_t tilebase, int row0, int ks, int lane) {
    const int sub = lane >> 3;
    const int row = row0 + (lane & 7) + ((sub & 1) << 3);
    const int ck  = ks * 2 + (sub >> 1);
    const int swz = ck ^ ((row >> 1) & 3);
    return tilebase + row * 64 + swz * 16;
}

__device__ __forceinline__ void split2(float a, __nv_bfloat16& h, __nv_bfloat16& l) {
    h = __float2bfloat16(a);
    l = __float2bfloat16(a - __bfloat162float(h));
}

// ---------------------------------------------------------------------------
// Prep: all 3 weight transposes in one launch. W[k][n] -> Wt_hi[n][k], Wt_lo[n][k]
// ---------------------------------------------------------------------------
__global__ __launch_bounds__(256)
void transpose_all_kernel(const float* __restrict__ W0, __nv_bfloat16* __restrict__ T0h, __nv_bfloat16* __restrict__ T0l,
                          const float* __restrict__ W1, __nv_bfloat16* __restrict__ T1h, __nv_bfloat16* __restrict__ T1l,
                          const float* __restrict__ W2, __nv_bfloat16* __restrict__ T2h, __nv_bfloat16* __restrict__ T2l)
{
    __shared__ float tile[32][33];
    const float* W = (blockIdx.z == 0) ? W0 : (blockIdx.z == 1) ? W1 : W2;
    __nv_bfloat16* Th = (blockIdx.z == 0) ? T0h : (blockIdx.z == 1) ? T1h : T2h;
    __nv_bfloat16* Tl = (blockIdx.z == 0) ? T0l : (blockIdx.z == 1) ? T1l : T2l;

    const int n0 = blockIdx.x * 32, k0 = blockIdx.y * 32;
    const int tx = threadIdx.x & 31, ty = threadIdx.x >> 5;   // 32 x 8
    #pragma unroll
    for (int i = 0; i < 4; ++i)
        tile[ty + i * 8][tx] = W[(size_t)(k0 + ty + i * 8) * HH + n0 + tx];
    __syncthreads();
    #pragma unroll
    for (int i = 0; i < 4; ++i) {
        const float v = tile[tx][ty + i * 8];
        __nv_bfloat16 h, l; split2(v, h, l);
        Th[(size_t)(n0 + ty + i * 8) * HH + k0 + tx] = h;
        Tl[(size_t)(n0 + ty + i * 8) * HH + k0 + tx] = l;
    }
}

// ---------------------------------------------------------------------------
// Fused x-split + windowed msg via running prefix scan.
// msg_t = 0.5*(S_all + S_same)/cnt over valid window [t-wp, t+wf] ∩ [0, L-1].
// S_all from prefix of valid x rows; S_same via prefix of speaker-0 rows.
// Grid: (H/128, T/SC_TC, B), block 128 (one column per thread).
// ---------------------------------------------------------------------------
__global__ __launch_bounds__(128)
void scan_msg_kernel(const float* __restrict__ x,
                     const float* __restrict__ qmask,
                     const int* __restrict__ dia_len,
                     const int* __restrict__ wp_p,
                     const int* __restrict__ wf_p,
                     __nv_bfloat16* __restrict__ xh, __nv_bfloat16* __restrict__ xl,
                     __nv_bfloat16* __restrict__ mh, __nv_bfloat16* __restrict__ ml)
{
    __shared__ float2 ring[RING_MAX][128];

    const int tid = threadIdx.x;
    const int col = blockIdx.x * 128 + tid;
    const int t_start = blockIdx.y * SC_TC;
    const int t_end = t_start + SC_TC - 1;
    const int b = blockIdx.z;
    const int wp = *wp_p, wf = *wf_p;
    const int nw = wp + wf + 1;       // ring depth (<= RING_MAX)
    const int L = dia_len[b];

    int ts = t_start - wp - 1; if (ts < 0) ts = 0;
    const int t_lastp = t_end + wf;   // may exceed T-1; those contribute 0

    float p_all = 0.f, p_s0 = 0.f;
    int rs = 0;

    for (int tp = ts; tp <= t_lastp; ++tp) {
        // P[tp - nw], written nw iterations ago (read before overwrite)
        const float2 oldP = ring[rs][tid];

        if (tp < TT) {
            const size_t o = ((size_t)b * TT + tp) * HH + col;
            const float xr = __ldg(x + o);
            if (tp >= t_start && tp <= t_end) {
                __nv_bfloat16 h, l; split2(xr, h, l);
                xh[o] = h; xl[o] = l;
            }
            if (tp < L) {
                const float q0 = __ldg(qmask + ((size_t)(b * TT + tp) << 1));
                const float q1 = __ldg(qmask + ((size_t)(b * TT + tp) << 1) + 1);
                p_all += xr;
                if (!(q1 > q0)) p_s0 += xr;
            }
        }
        ring[rs][tid] = make_float2(p_all, p_s0);
        if (++rs == nw) rs = 0;

        const int t = tp - wf;
        if (t >= t_start && t <= t_end) {
            float s_all = p_all, s_s0 = p_s0;
            if (t - wp - 1 >= 0) { s_all -= oldP.x; s_s0 -= oldP.y; }
            const float q0 = __ldg(qmask + ((size_t)(b * TT + t) << 1));
            const float q1 = __ldg(qmask + ((size_t)(b * TT + t) << 1) + 1);
            const float s_same = (q1 > q0) ? (s_all - s_s0) : s_s0;
            int hi = t + wf; if (hi > L - 1) hi = L - 1;
            int lo = t - wp; if (lo < 0) lo = 0;
            int cnt = hi - lo + 1; if (cnt < 1) cnt = 1;
            const float m = 0.5f * (s_all + s_same) / (float)cnt;
            __nv_bfloat16 h, l; split2(m, h, l);
            const size_t o = ((size_t)b * TT + t) * HH + col;
            mh[o] = h; ml[o] = l;
        }
    }
}

// ---------------------------------------------------------------------------
// HMMA GEMM, 3-stage cp.async, CTA 256x128, 8 warps (64x64 each).
// D = sum_g (Ah@Bh^T + Ah@Bl^T + Al@Bh^T)
// mode 0: h = D + b0 + b1; out = nv ? h : x; relu -> out_h/out_l
// mode 1: z = x + D + b0 -> out_f
// ---------------------------------------------------------------------------
__device__ __forceinline__ void load_tile_ca(uint32_t dstbase,
                                             const __nv_bfloat16* __restrict__ src,
                                             int r0, int k0, int tid, int niter)
{
    #pragma unroll
    for (int j = 0; j < 4; ++j) {
        if (j >= niter) break;
        const int cc  = j * 256 + tid;
        const int row = cc >> 2;
        const int ck  = cc & 3;
        const int swz = ck ^ ((row >> 1) & 3);
        cp16(dstbase + row * 64 + swz * 16,
             src + (size_t)(r0 + row) * HH + k0 + ck * 8);
    }
}

__global__ __launch_bounds__(256, 1)
void hmma_gemm_kernel(const __nv_bfloat16* __restrict__ Ah0, const __nv_bfloat16* __restrict__ Al0,
                      const __nv_bfloat16* __restrict__ Bh0, const __nv_bfloat16* __restrict__ Bl0,
                      const __nv_bfloat16* __restrict__ Ah1, const __nv_bfloat16* __restrict__ Al1,
                      const __nv_bfloat16* __restrict__ Bh1, const __nv_bfloat16* __restrict__ Bl1,
                      int ngroups,
                      const float* __restrict__ b0v, const float* __restrict__ b1v,
                      const float* __restrict__ x, const int* __restrict__ dia_len,
                      int mode,
                      __nv_bfloat16* __restrict__ out_h, __nv_bfloat16* __restrict__ out_l,
                      float* __restrict__ out_f)
{
    extern __shared__ char smem[];
    const uint32_t sbase = smem_u32(smem);
    const int tid  = threadIdx.x;
    const int wid  = tid >> 5, lane = tid & 31;
    const int warp_m = wid & 3;      // 4 warps along M (64 rows each)
    const int warp_n = wid >> 2;     // 2 warps along N (64 cols each)
    const int n0 = blockIdx.x * BN;
    const int m0 = blockIdx.y * BM;

    float acc[4][8][4];
    #pragma unroll
    for (int i = 0; i < 4; ++i)
        #pragma unroll
        for (int j = 0; j < 8; ++j)
            #pragma unroll
            for (int k = 0; k < 4; ++k) acc[i][j][k] = 0.f;

    const int NC = ngroups * (HH / BKE);

    auto do_load = [&](int cc, int stage) {
        const __nv_bfloat16* Ah = (cc < 32) ? Ah0 : Ah1;
        const __nv_bfloat16* Al = (cc < 32) ? Al0 : Al1;
        const __nv_bfloat16* Bh = (cc < 32) ? Bh0 : Bh1;
        const __nv_bfloat16* Bl = (cc < 32) ? Bl0 : Bl1;
        const int k0 = (cc & 31) * BKE;
        const uint32_t sb = sbase + stage * STAGE_BYTES;
        load_tile_ca(sb,         Ah, m0, k0, tid, 4);   // 256x32
        load_tile_ca(sb + 16384, Al, m0, k0, tid, 4);
        load_tile_ca(sb + 32768, Bh, n0, k0, tid, 2);   // 128x32
        load_tile_ca(sb + 40960, Bl, n0, k0, tid, 2);
        asm volatile("cp.async.commit_group;" ::: "memory");
    };

    do_load(0, 0);
    do_load(1, 1);

    int stage = 0;
    int nstage = 2;
    for (int c = 0; c < NC; ++c) {
        if (c == NC - 1) { asm volatile("cp.async.wait_group 0;" ::: "memory"); }
        else             { asm volatile("cp.async.wait_group 1;" ::: "memory"); }
        __syncthreads();

        if (c + 2 < NC) do_load(c + 2, nstage);

        const uint32_t sb  = sbase + stage * STAGE_BYTES;
        const uint32_t sAh = sb, sAl = sb + 16384, sBh = sb + 32768, sBl = sb + 40960;

        #pragma unroll
        for (int ks = 0; ks < 2; ++ks) {
            uint32_t ah[4][4], al[4][4];
            #pragma unroll
            for (int mf = 0; mf < 4; ++mf) {
                ldsm4(ah[mf], ldsm_addr(sAh, warp_m * 64 + mf * 16, ks, lane));
                ldsm4(al[mf], ldsm_addr(sAl, warp_m * 64 + mf * 16, ks, lane));
            }
            #pragma unroll
            for (int nb = 0; nb < 4; ++nb) {
                uint32_t bh[4], bl[4];
                ldsm4(bh, ldsm_addr(sBh, warp_n * 64 + nb * 16, ks, lane));
                ldsm4(bl, ldsm_addr(sBl, warp_n * 64 + nb * 16, ks, lane));
                #pragma unroll
                for (int mf = 0; mf < 4; ++mf) {
                    float* c0 = acc[mf][nb * 2];
                    float* c1 = acc[mf][nb * 2 + 1];
                    mma16816(c0, ah[mf], bh[0], bh[2]);
                    mma16816(c1, ah[mf], bh[1], bh[3]);
                    mma16816(c0, ah[mf], bl[0], bl[2]);
                    mma16816(c1, ah[mf], bl[1], bl[3]);
                    mma16816(c0, al[mf], bh[0], bh[2]);
                    mma16816(c1, al[mf], bh[1], bh[3]);
                }
            }
        }
        stage = (stage == NSTAGE - 1) ? 0 : stage + 1;
        nstage = (nstage == NSTAGE - 1) ? 0 : nstage + 1;
    }

    // ---- epilogue ----
    const int groupID = lane >> 2;
    const int qc = (lane & 3) * 2;

    float2 biasv[8];
    #pragma unroll
    for (int nf = 0; nf < 8; ++nf) {
        const int col = n0 + warp_n * 64 + nf * 8 + qc;
        if (mode == 0) {
            biasv[nf].x = __ldg(b0v + col)     + __ldg(b1v + col);
            biasv[nf].y = __ldg(b0v + col + 1) + __ldg(b1v + col + 1);
        } else {
            biasv[nf].x = __ldg(b0v + col);
            biasv[nf].y = __ldg(b0v + col + 1);
        }
    }

    #pragma unroll
    for (int mf = 0; mf < 4; ++mf) {
        #pragma unroll
        for (int half = 0; half < 2; ++half) {
            const int m = m0 + warp_m * 64 + mf * 16 + groupID + half * 8;
            const size_t rb = (size_t)m * HH;
            const bool nv = (mode == 0) ? ((m & (TT - 1)) < dia_len[m >> 10]) : true;
            #pragma unroll
            for (int nf = 0; nf < 8; ++nf) {
                const int col = n0 + warp_n * 64 + nf * 8 + qc;
                float v0 = acc[mf][nf][half * 2 + 0] + biasv[nf].x;
                float v1 = acc[mf][nf][half * 2 + 1] + biasv[nf].y;
                if (mode == 0) {
                    if (!nv) {
                        const float2 xv = *(const float2*)(x + rb + col);
                        v0 = xv.x; v1 = xv.y;
                    }
                    v0 = fmaxf(v0, 0.f); v1 = fmaxf(v1, 0.f);
                    __nv_bfloat162 hp, lp;
                    split2(v0, hp.x, lp.x); split2(v1, hp.y, lp.y);
                    *(__nv_bfloat162*)(out_h + rb + col) = hp;
                    *(__nv_bfloat162*)(out_l + rb + col) = lp;
                } else {
                    const float2 xv = *(const float2*)(x + rb + col);
                    float2 o; o.x = xv.x + v0; o.y = xv.y + v1;
                    *(float2*)(out_f + rb + col) = o;
                }
            }
        }
    }
}

// ---------------------------------------------------------------------------
// LayerNorm
// ---------------------------------------------------------------------------
__global__ __launch_bounds__(256)
void ln_kernel(const float* __restrict__ z,
               const float* __restrict__ gamma,
               const float* __restrict__ beta,
               float* __restrict__ out)
{
    __shared__ float sh_s[8], sh_ss[8];
    __shared__ float sh_mean, sh_inv;

    const int row = blockIdx.x;
    const int tid = threadIdx.x;
    const float4 v = ((const float4*)z)[(size_t)row * (HH / 4) + tid];

    float s  = v.x + v.y + v.z + v.w;
    float ss = v.x * v.x + v.y * v.y + v.z * v.z + v.w * v.w;
    #pragma unroll
    for (int off = 16; off; off >>= 1) {
        s  += __shfl_xor_sync(0xFFFFFFFFu, s,  off);
        ss += __shfl_xor_sync(0xFFFFFFFFu, ss, off);
    }
    const int wid = tid >> 5, lane = tid & 31;
    if (lane == 0) { sh_s[wid] = s; sh_ss[wid] = ss; }
    __syncthreads();
    if (tid == 0) {
        float ts = 0.f, tss = 0.f;
        #pragma unroll
        for (int w = 0; w < 8; ++w) { ts += sh_s[w]; tss += sh_ss[w]; }
        const float mean = ts * (1.f / HH);
        const float var  = tss * (1.f / HH) - mean * mean;
        sh_mean = mean;
        sh_inv  = rsqrtf(var + LN_EPS);
    }
    __syncthreads();
    const float mean = sh_mean, inv = sh_inv;

    const float4 g  = ((const float4*)gamma)[tid];
    const float4 bt = ((const float4*)beta)[tid];
    float4 o;
    o.x = g.x * (v.x - mean) * inv + bt.x;
    o.y = g.y * (v.y - mean) * inv + bt.y;
    o.z = g.z * (v.z - mean) * inv + bt.z;
    o.w = g.w * (v.w - mean) * inv + bt.w;
    ((float4*)out)[(size_t)row * (HH / 4) + tid] = o;
}

// ---------------------------------------------------------------------------
// Launch
// ---------------------------------------------------------------------------
extern "C" void kernel_launch(void* const* d_in, const int* in_sizes, int n_in,
                              void* d_out, int out_size)
{
    const float* x      = (const float*)d_in[0];
    const float* qmask  = (const float*)d_in[1];
    const int*   dia    = (const int*)  d_in[2];
    const int*   wp     = (const int*)  d_in[3];
    const int*   wf     = (const int*)  d_in[4];
    const float* W_msg  = (const float*)d_in[5];
    const float* b_msg  = (const float*)d_in[6];
    const float* W_self = (const float*)d_in[7];
    const float* b_self = (const float*)d_in[8];
    const float* W_out  = (const float*)d_in[9];
    const float* b_out  = (const float*)d_in[10];
    const float* gamma  = (const float*)d_in[11];
    const float* beta   = (const float*)d_in[12];
    float* out = (float*)d_out;

    __nv_bfloat16 *xh, *xl, *mh, *ml, *rh, *rl;
    __nv_bfloat16 *wsh, *wsl, *wmh, *wml, *woh, *wol;
    float* z;
    cudaGetSymbolAddress((void**)&xh, g_xh);   cudaGetSymbolAddress((void**)&xl, g_xl);
    cudaGetSymbolAddress((void**)&mh, g_mh);   cudaGetSymbolAddress((void**)&ml, g_ml);
    cudaGetSymbolAddress((void**)&rh, g_rh);   cudaGetSymbolAddress((void**)&rl, g_rl);
    cudaGetSymbolAddress((void**)&wsh, g_wst_h); cudaGetSymbolAddress((void**)&wsl, g_wst_l);
    cudaGetSymbolAddress((void**)&wmh, g_wmt_h); cudaGetSymbolAddress((void**)&wml, g_wmt_l);
    cudaGetSymbolAddress((void**)&woh, g_wot_h); cudaGetSymbolAddress((void**)&wol, g_wot_l);
    cudaGetSymbolAddress((void**)&z, g_z);

    cudaFuncSetAttribute(hmma_gemm_kernel,
                         cudaFuncAttributeMaxDynamicSharedMemorySize, GEMM_SMEM);

    // prep
    dim3 tgrid(HH / 32, HH / 32, 3);
    transpose_all_kernel<<<tgrid, 256>>>(W_self, wsh, wsl, W_msg, wmh, wml, W_out, woh, wol);
    dim3 sgrid(HH / 128, TT / SC_TC, BB);
    scan_msg_kernel<<<sgrid, 128>>>(x, qmask, dia, wp, wf, xh, xl, mh, ml);

    dim3 ggrid(HH / BN, MM / BM);   // (8, 32)
    // GEMM1: x@W_self + msg@W_msg -> relu/select -> r (hi/lo)
    hmma_gemm_kernel<<<ggrid, 256, GEMM_SMEM>>>(
        xh, xl, wsh, wsl, mh, ml, wmh, wml, 2,
        b_self, b_msg, x, dia, 0, rh, rl, nullptr);
    // GEMM2: r@W_out + b_out + x -> z (fp32)
    hmma_gemm_kernel<<<ggrid, 256, GEMM_SMEM>>>(
        rh, rl, woh, wol, nullptr, nullptr, nullptr, nullptr, 1,
        b_out, nullptr, x, dia, 1, nullptr, nullptr, z);

    ln_kernel<<<MM, 256>>>(z, gamma, beta, out);
}

// round 6
// speedup vs baseline: 1.1336x; 1.1336x over previous
#include <cuda_runtime.h>
#include <cuda_bf16.h>
#include <cstdint>

// Problem constants
#define BB 8
#define TT 1024
#define HH 1024
#define MM (BB * TT)      // 8192 rows
#define LN_EPS 1e-5f

// HMMA GEMM tiling: CTA 256x128, 16 warps of 64x32
#define BM 256
#define BN 128
#define BKE 32                 // bf16 K elems per stage
#define NSTAGE 4
#define STAGE_BYTES 49152      // A(hi+lo): 2x16KB, B(hi+lo): 2x8KB
#define GEMM_SMEM (NSTAGE * STAGE_BYTES)   // 196608
#define GTH 512

// ---------------------------------------------------------------------------
// Scratch (device globals — allocation-free rule)
// ---------------------------------------------------------------------------
__device__ __nv_bfloat16 g_xh[MM * HH], g_xl[MM * HH];
__device__ __nv_bfloat16 g_mh[MM * HH], g_ml[MM * HH];
__device__ __nv_bfloat16 g_rh[MM * HH], g_rl[MM * HH];
__device__ __nv_bfloat16 g_wst_h[HH * HH], g_wst_l[HH * HH];   // W_self^T [n][k]
__device__ __nv_bfloat16 g_wmt_h[HH * HH], g_wmt_l[HH * HH];   // W_msg^T
__device__ __nv_bfloat16 g_wot_h[HH * HH], g_wot_l[HH * HH];   // W_out^T
__device__ float g_z[MM * HH];

// ---------------------------------------------------------------------------
// PTX helpers (baseline ISA — compiles at compute_103)
// ---------------------------------------------------------------------------
__device__ __forceinline__ uint32_t smem_u32(const void* p) {
    uint32_t a;
    asm("{ .reg .u64 t; cvta.to.shared.u64 t, %1; cvt.u32.u64 %0, t; }"
        : "=r"(a) : "l"(p));
    return a;
}
__device__ __forceinline__ void cp16(uint32_t dst, const void* src) {
    asm volatile("cp.async.cg.shared.global [%0], [%1], 16;" :: "r"(dst), "l"(src));
}
__device__ __forceinline__ void ldsm4(uint32_t* r, uint32_t a) {
    asm volatile("ldmatrix.sync.aligned.m8n8.x4.shared.b16 {%0,%1,%2,%3}, [%4];"
        : "=r"(r[0]), "=r"(r[1]), "=r"(r[2]), "=r"(r[3]) : "r"(a));
}
__device__ __forceinline__ void mma16816(float* c, const uint32_t* a,
                                         uint32_t b0, uint32_t b1) {
    asm volatile(
        "mma.sync.aligned.m16n8k16.row.col.f32.bf16.bf16.f32 "
        "{%0,%1,%2,%3}, {%4,%5,%6,%7}, {%8,%9}, {%0,%1,%2,%3};"
        : "+f"(c[0]), "+f"(c[1]), "+f"(c[2]), "+f"(c[3])
        : "r"(a[0]), "r"(a[1]), "r"(a[2]), "r"(a[3]), "r"(b0), "r"(b1));
}

// Tile rows are 64B (32 bf16); 16B chunk index XOR-swizzled with (row>>1)&3.
__device__ __forceinline__ uint32_t ldsm_addr(uint32_t tilebase, int row0, int ks, int lane) {
    const int sub = lane >> 3;
    const int row = row0 + (lane & 7) + ((sub & 1) << 3);
    const int ck  = ks * 2 + (sub >> 1);
    const int swz = ck ^ ((row >> 1) & 3);
    return tilebase + row * 64 + swz * 16;
}

__device__ __forceinline__ void split2(float a, __nv_bfloat16& h, __nv_bfloat16& l) {
    h = __float2bfloat16(a);
    l = __float2bfloat16(a - __bfloat162float(h));
}

// ---------------------------------------------------------------------------
// Prep: all 3 weight transposes in one launch. W[k][n] -> Wt_hi[n][k], Wt_lo[n][k]
// ---------------------------------------------------------------------------
__global__ __launch_bounds__(256)
void transpose_all_kernel(const float* __restrict__ W0, __nv_bfloat16* __restrict__ T0h, __nv_bfloat16* __restrict__ T0l,
                          const float* __restrict__ W1, __nv_bfloat16* __restrict__ T1h, __nv_bfloat16* __restrict__ T1l,
                          const float* __restrict__ W2, __nv_bfloat16* __restrict__ T2h, __nv_bfloat16* __restrict__ T2l)
{
    __shared__ float tile[32][33];
    const float* W = (blockIdx.z == 0) ? W0 : (blockIdx.z == 1) ? W1 : W2;
    __nv_bfloat16* Th = (blockIdx.z == 0) ? T0h : (blockIdx.z == 1) ? T1h : T2h;
    __nv_bfloat16* Tl = (blockIdx.z == 0) ? T0l : (blockIdx.z == 1) ? T1l : T2l;

    const int n0 = blockIdx.x * 32, k0 = blockIdx.y * 32;
    const int tx = threadIdx.x & 31, ty = threadIdx.x >> 5;   // 32 x 8
    #pragma unroll
    for (int i = 0; i < 4; ++i)
        tile[ty + i * 8][tx] = W[(size_t)(k0 + ty + i * 8) * HH + n0 + tx];
    __syncthreads();
    #pragma unroll
    for (int i = 0; i < 4; ++i) {
        const float v = tile[tx][ty + i * 8];
        __nv_bfloat16 h, l; split2(v, h, l);
        Th[(size_t)(n0 + ty + i * 8) * HH + k0 + tx] = h;
        Tl[(size_t)(n0 + ty + i * 8) * HH + k0 + tx] = l;
    }
}

// ---------------------------------------------------------------------------
// Fused: x split (hi/lo) + windowed speaker-weighted msg (hi/lo). One row/block.
// (R4 gather version — best measured.)
// ---------------------------------------------------------------------------
__global__ __launch_bounds__(256)
void split_msg_kernel(const float* __restrict__ x,
                      const float* __restrict__ qmask,
                      const int* __restrict__ dia_len,
                      const int* __restrict__ wp_p,
                      const int* __restrict__ wf_p,
                      __nv_bfloat16* __restrict__ xh, __nv_bfloat16* __restrict__ xl,
                      __nv_bfloat16* __restrict__ mh, __nv_bfloat16* __restrict__ ml)
{
    __shared__ float s_w[64];
    __shared__ int   s_nw;

    const int row = blockIdx.x;
    const int b   = row >> 10;
    const int t   = row & (TT - 1);
    const int tid = threadIdx.x;

    const int wp = *wp_p;
    const int wf = *wf_p;
    const int nw = wp + wf + 1;
    if (tid == 0) s_nw = nw;
    const int L = dia_len[b];

    if (tid < nw) {
        const int idx = t + tid - wp;
        float w = 0.f;
        if (idx >= 0 && idx <= L - 1) {
            const float* qt = qmask + ((size_t)row << 1);
            const float* qn = qmask + (((size_t)(b * TT + idx)) << 1);
            const int sp_t = qt[1] > qt[0];
            const int sp_n = qn[1] > qn[0];
            w = (sp_t == sp_n) ? 1.0f : 0.5f;
        }
        s_w[tid] = w;
    }
    __syncthreads();

    float cnt = 0.f;
    const int nw_s = s_nw;
    for (int o = 0; o < nw_s; ++o) cnt += (s_w[o] > 0.f) ? 1.f : 0.f;
    cnt = fmaxf(cnt, 1.f);
    const float inv = 1.f / cnt;

    // split x row
    {
        const size_t i = (size_t)row * HH + tid * 4;
        const float4 v = *(const float4*)(x + i);
        __nv_bfloat162 h0, h1, l0, l1;
        split2(v.x, h0.x, l0.x); split2(v.y, h0.y, l0.y);
        split2(v.z, h1.x, l1.x); split2(v.w, h1.y, l1.y);
        *(__nv_bfloat162*)(xh + i)     = h0;
        *(__nv_bfloat162*)(xh + i + 2) = h1;
        *(__nv_bfloat162*)(xl + i)     = l0;
        *(__nv_bfloat162*)(xl + i + 2) = l1;
    }

    // msg row
    float4 acc = make_float4(0.f, 0.f, 0.f, 0.f);
    const float4* x4 = (const float4*)x;
    for (int o = 0; o < nw_s; ++o) {
        const float w = s_w[o];
        if (w != 0.f) {
            const int idx = t + o - wp;
            const float4 v = x4[((size_t)(b * TT + idx)) * (HH / 4) + tid];
            acc.x += w * v.x; acc.y += w * v.y;
            acc.z += w * v.z; acc.w += w * v.w;
        }
    }
    acc.x *= inv; acc.y *= inv; acc.z *= inv; acc.w *= inv;

    const size_t base = (size_t)row * HH + tid * 4;
    __nv_bfloat162 h0, h1, l0, l1;
    split2(acc.x, h0.x, l0.x); split2(acc.y, h0.y, l0.y);
    split2(acc.z, h1.x, l1.x); split2(acc.w, h1.y, l1.y);
    *(__nv_bfloat162*)(mh + base)     = h0;
    *(__nv_bfloat162*)(mh + base + 2) = h1;
    *(__nv_bfloat162*)(ml + base)     = l0;
    *(__nv_bfloat162*)(ml + base + 2) = l1;
}

// ---------------------------------------------------------------------------
// HMMA GEMM, 4-stage cp.async, CTA 256x128, 16 warps (64x32 each), 512 thr.
// D = sum_g (Ah@Bh^T + Ah@Bl^T + Al@Bh^T)
// mode 0: h = D + b0 + b1; out = nv ? h : x; relu -> out_h/out_l
// mode 1: z = x + D + b0 -> out_f
// ---------------------------------------------------------------------------
__device__ __forceinline__ void load_tile_ca(uint32_t dstbase,
                                             const __nv_bfloat16* __restrict__ src,
                                             int r0, int k0, int tid, int niter)
{
    #pragma unroll
    for (int j = 0; j < 2; ++j) {
        if (j >= niter) break;
        const int cc  = j * GTH + tid;
        const int row = cc >> 2;
        const int ck  = cc & 3;
        const int swz = ck ^ ((row >> 1) & 3);
        cp16(dstbase + row * 64 + swz * 16,
             src + (size_t)(r0 + row) * HH + k0 + ck * 8);
    }
}

__global__ __launch_bounds__(GTH, 1)
void hmma_gemm_kernel(const __nv_bfloat16* __restrict__ Ah0, const __nv_bfloat16* __restrict__ Al0,
                      const __nv_bfloat16* __restrict__ Bh0, const __nv_bfloat16* __restrict__ Bl0,
                      const __nv_bfloat16* __restrict__ Ah1, const __nv_bfloat16* __restrict__ Al1,
                      const __nv_bfloat16* __restrict__ Bh1, const __nv_bfloat16* __restrict__ Bl1,
                      int ngroups,
                      const float* __restrict__ b0v, const float* __restrict__ b1v,
                      const float* __restrict__ x, const int* __restrict__ dia_len,
                      int mode,
                      __nv_bfloat16* __restrict__ out_h, __nv_bfloat16* __restrict__ out_l,
                      float* __restrict__ out_f)
{
    extern __shared__ char smem[];
    const uint32_t sbase = smem_u32(smem);
    const int tid  = threadIdx.x;
    const int wid  = tid >> 5, lane = tid & 31;
    const int warp_m = wid >> 2;     // 4 groups along M (64 rows each)
    const int warp_n = wid & 3;      // 4 groups along N (32 cols each)
    const int n0 = blockIdx.x * BN;
    const int m0 = blockIdx.y * BM;

    float acc[4][4][4];
    #pragma unroll
    for (int i = 0; i < 4; ++i)
        #pragma unroll
        for (int j = 0; j < 4; ++j)
            #pragma unroll
            for (int k = 0; k < 4; ++k) acc[i][j][k] = 0.f;

    const int NC = ngroups * (HH / BKE);

    auto do_load = [&](int cc, int stage) {
        const __nv_bfloat16* Ah = (cc < 32) ? Ah0 : Ah1;
        const __nv_bfloat16* Al = (cc < 32) ? Al0 : Al1;
        const __nv_bfloat16* Bh = (cc < 32) ? Bh0 : Bh1;
        const __nv_bfloat16* Bl = (cc < 32) ? Bl0 : Bl1;
        const int k0 = (cc & 31) * BKE;
        const uint32_t sb = sbase + stage * STAGE_BYTES;
        load_tile_ca(sb,         Ah, m0, k0, tid, 2);   // 256x32
        load_tile_ca(sb + 16384, Al, m0, k0, tid, 2);
        load_tile_ca(sb + 32768, Bh, n0, k0, tid, 1);   // 128x32
        load_tile_ca(sb + 40960, Bl, n0, k0, tid, 1);
        asm volatile("cp.async.commit_group;" ::: "memory");
    };

    // prologue: fill NSTAGE-1 stages
    do_load(0, 0);
    do_load(1, 1);
    do_load(2, 2);

    int stage = 0;
    int nstage = 3;
    for (int c = 0; c < NC; ++c) {
        const int rem = NC - 1 - c;
        if (rem >= 2)      { asm volatile("cp.async.wait_group 2;" ::: "memory"); }
        else if (rem == 1) { asm volatile("cp.async.wait_group 1;" ::: "memory"); }
        else               { asm volatile("cp.async.wait_group 0;" ::: "memory"); }
        __syncthreads();

        if (c + 3 < NC) do_load(c + 3, nstage);

        const uint32_t sb  = sbase + stage * STAGE_BYTES;
        const uint32_t sAh = sb, sAl = sb + 16384, sBh = sb + 32768, sBl = sb + 40960;

        #pragma unroll
        for (int ks = 0; ks < 2; ++ks) {
            uint32_t ah[4][4], al[4][4];
            #pragma unroll
            for (int mf = 0; mf < 4; ++mf) {
                ldsm4(ah[mf], ldsm_addr(sAh, warp_m * 64 + mf * 16, ks, lane));
                ldsm4(al[mf], ldsm_addr(sAl, warp_m * 64 + mf * 16, ks, lane));
            }
            #pragma unroll
            for (int nb = 0; nb < 2; ++nb) {
                uint32_t bh[4], bl[4];
                ldsm4(bh, ldsm_addr(sBh, warp_n * 32 + nb * 16, ks, lane));
                ldsm4(bl, ldsm_addr(sBl, warp_n * 32 + nb * 16, ks, lane));
                #pragma unroll
                for (int mf = 0; mf < 4; ++mf) {
                    float* c0 = acc[mf][nb * 2];
                    float* c1 = acc[mf][nb * 2 + 1];
                    mma16816(c0, ah[mf], bh[0], bh[2]);
                    mma16816(c1, ah[mf], bh[1], bh[3]);
                    mma16816(c0, ah[mf], bl[0], bl[2]);
                    mma16816(c1, ah[mf], bl[1], bl[3]);
                    mma16816(c0, al[mf], bh[0], bh[2]);
                    mma16816(c1, al[mf], bh[1], bh[3]);
                }
            }
        }
        stage = (stage == NSTAGE - 1) ? 0 : stage + 1;
        nstage = (nstage == NSTAGE - 1) ? 0 : nstage + 1;
    }

    // ---- epilogue ----
    const int groupID = lane >> 2;
    const int qc = (lane & 3) * 2;

    float2 biasv[4];
    #pragma unroll
    for (int nf = 0; nf < 4; ++nf) {
        const int col = n0 + warp_n * 32 + nf * 8 + qc;
        if (mode == 0) {
            biasv[nf].x = __ldg(b0v + col)     + __ldg(b1v + col);
            biasv[nf].y = __ldg(b0v + col + 1) + __ldg(b1v + col + 1);
        } else {
            biasv[nf].x = __ldg(b0v + col);
            biasv[nf].y = __ldg(b0v + col + 1);
        }
    }

    #pragma unroll
    for (int mf = 0; mf < 4; ++mf) {
        #pragma unroll
        for (int half = 0; half < 2; ++half) {
            const int m = m0 + warp_m * 64 + mf * 16 + groupID + half * 8;
            const size_t rb = (size_t)m * HH;
            const bool nv = (mode == 0) ? ((m & (TT - 1)) < dia_len[m >> 10]) : true;
            #pragma unroll
            for (int nf = 0; nf < 4; ++nf) {
                const int col = n0 + warp_n * 32 + nf * 8 + qc;
                float v0 = acc[mf][nf][half * 2 + 0] + biasv[nf].x;
                float v1 = acc[mf][nf][half * 2 + 1] + biasv[nf].y;
                if (mode == 0) {
                    if (!nv) {
                        const float2 xv = *(const float2*)(x + rb + col);
                        v0 = xv.x; v1 = xv.y;
                    }
                    v0 = fmaxf(v0, 0.f); v1 = fmaxf(v1, 0.f);
                    __nv_bfloat162 hp, lp;
                    split2(v0, hp.x, lp.x); split2(v1, hp.y, lp.y);
                    *(__nv_bfloat162*)(out_h + rb + col) = hp;
                    *(__nv_bfloat162*)(out_l + rb + col) = lp;
                } else {
                    const float2 xv = *(const float2*)(x + rb + col);
                    float2 o; o.x = xv.x + v0; o.y = xv.y + v1;
                    *(float2*)(out_f + rb + col) = o;
                }
            }
        }
    }
}

// ---------------------------------------------------------------------------
// LayerNorm
// ---------------------------------------------------------------------------
__global__ __launch_bounds__(256)
void ln_kernel(const float* __restrict__ z,
               const float* __restrict__ gamma,
               const float* __restrict__ beta,
               float* __restrict__ out)
{
    __shared__ float sh_s[8], sh_ss[8];
    __shared__ float sh_mean, sh_inv;

    const int row = blockIdx.x;
    const int tid = threadIdx.x;
    const float4 v = ((const float4*)z)[(size_t)row * (HH / 4) + tid];

    float s  = v.x + v.y + v.z + v.w;
    float ss = v.x * v.x + v.y * v.y + v.z * v.z + v.w * v.w;
    #pragma unroll
    for (int off = 16; off; off >>= 1) {
        s  += __shfl_xor_sync(0xFFFFFFFFu, s,  off);
        ss += __shfl_xor_sync(0xFFFFFFFFu, ss, off);
    }
    const int wid = tid >> 5, lane = tid & 31;
    if (lane == 0) { sh_s[wid] = s; sh_ss[wid] = ss; }
    __syncthreads();
    if (tid == 0) {
        float ts = 0.f, tss = 0.f;
        #pragma unroll
        for (int w = 0; w < 8; ++w) { ts += sh_s[w]; tss += sh_ss[w]; }
        const float mean = ts * (1.f / HH);
        const float var  = tss * (1.f / HH) - mean * mean;
        sh_mean = mean;
        sh_inv  = rsqrtf(var + LN_EPS);
    }
    __syncthreads();
    const float mean = sh_mean, inv = sh_inv;

    const float4 g  = ((const float4*)gamma)[tid];
    const float4 bt = ((const float4*)beta)[tid];
    float4 o;
    o.x = g.x * (v.x - mean) * inv + bt.x;
    o.y = g.y * (v.y - mean) * inv + bt.y;
    o.z = g.z * (v.z - mean) * inv + bt.z;
    o.w = g.w * (v.w - mean) * inv + bt.w;
    ((float4*)out)[(size_t)row * (HH / 4) + tid] = o;
}

// ---------------------------------------------------------------------------
// Launch
// ---------------------------------------------------------------------------
extern "C" void kernel_launch(void* const* d_in, const int* in_sizes, int n_in,
                              void* d_out, int out_size)
{
    const float* x      = (const float*)d_in[0];
    const float* qmask  = (const float*)d_in[1];
    const int*   dia    = (const int*)  d_in[2];
    const int*   wp     = (const int*)  d_in[3];
    const int*   wf     = (const int*)  d_in[4];
    const float* W_msg  = (const float*)d_in[5];
    const float* b_msg  = (const float*)d_in[6];
    const float* W_self = (const float*)d_in[7];
    const float* b_self = (const float*)d_in[8];
    const float* W_out  = (const float*)d_in[9];
    const float* b_out  = (const float*)d_in[10];
    const float* gamma  = (const float*)d_in[11];
    const float* beta   = (const float*)d_in[12];
    float* out = (float*)d_out;

    __nv_bfloat16 *xh, *xl, *mh, *ml, *rh, *rl;
    __nv_bfloat16 *wsh, *wsl, *wmh, *wml, *woh, *wol;
    float* z;
    cudaGetSymbolAddress((void**)&xh, g_xh);   cudaGetSymbolAddress((void**)&xl, g_xl);
    cudaGetSymbolAddress((void**)&mh, g_mh);   cudaGetSymbolAddress((void**)&ml, g_ml);
    cudaGetSymbolAddress((void**)&rh, g_rh);   cudaGetSymbolAddress((void**)&rl, g_rl);
    cudaGetSymbolAddress((void**)&wsh, g_wst_h); cudaGetSymbolAddress((void**)&wsl, g_wst_l);
    cudaGetSymbolAddress((void**)&wmh, g_wmt_h); cudaGetSymbolAddress((void**)&wml, g_wmt_l);
    cudaGetSymbolAddress((void**)&woh, g_wot_h); cudaGetSymbolAddress((void**)&wol, g_wot_l);
    cudaGetSymbolAddress((void**)&z, g_z);

    cudaFuncSetAttribute(hmma_gemm_kernel,
                         cudaFuncAttributeMaxDynamicSharedMemorySize, GEMM_SMEM);

    // prep
    dim3 tgrid(HH / 32, HH / 32, 3);
    transpose_all_kernel<<<tgrid, 256>>>(W_self, wsh, wsl, W_msg, wmh, wml, W_out, woh, wol);
    split_msg_kernel<<<MM, 256>>>(x, qmask, dia, wp, wf, xh, xl, mh, ml);

    dim3 ggrid(HH / BN, MM / BM);   // (8, 32)
    // GEMM1: x@W_self + msg@W_msg -> relu/select -> r (hi/lo)
    hmma_gemm_kernel<<<ggrid, GTH, GEMM_SMEM>>>(
        xh, xl, wsh, wsl, mh, ml, wmh, wml, 2,
        b_self, b_msg, x, dia, 0, rh, rl, nullptr);
    // GEMM2: r@W_out + b_out + x -> z (fp32)
    hmma_gemm_kernel<<<ggrid, GTH, GEMM_SMEM>>>(
        rh, rl, woh, wol, nullptr, nullptr, nullptr, nullptr, 1,
        b_out, nullptr, x, dia, 1, nullptr, nullptr, z);

    ln_kernel<<<MM, 256>>>(z, gamma, beta, out);
}

// round 7
// speedup vs baseline: 1.6276x; 1.4358x over previous
#include <cuda_runtime.h>
#include <cuda_fp16.h>
#include <cstdint>

// Problem constants
#define BB 8
#define TT 1024
#define HH 1024
#define MM (BB * TT)      // 8192 rows
#define LN_EPS 1e-5f

// HMMA GEMM tiling: CTA 256x128, 16 warps of 64x32
#define BM 256
#define BN 128
#define BKE 32                 // fp16 K elems per stage
#define NSTAGE 4
#define STAGE_BYTES 32768      // A: 16KB, B(hi+lo): 2x8KB
#define GEMM_SMEM (NSTAGE * STAGE_BYTES)   // 131072
#define GTH 512

// ---------------------------------------------------------------------------
// Scratch (device globals — allocation-free rule)
// ---------------------------------------------------------------------------
__device__ __half g_xh[MM * HH];
__device__ __half g_mh[MM * HH];
__device__ __half g_rh[MM * HH];
__device__ __half g_wst_h[HH * HH], g_wst_l[HH * HH];   // W_self^T [n][k] hi/lo
__device__ __half g_wmt_h[HH * HH], g_wmt_l[HH * HH];   // W_msg^T
__device__ __half g_wot_h[HH * HH], g_wot_l[HH * HH];   // W_out^T
__device__ float g_z[MM * HH];

// ---------------------------------------------------------------------------
// PTX helpers (baseline ISA — compiles at compute_103)
// ---------------------------------------------------------------------------
__device__ __forceinline__ uint32_t smem_u32(const void* p) {
    uint32_t a;
    asm("{ .reg .u64 t; cvta.to.shared.u64 t, %1; cvt.u32.u64 %0, t; }"
        : "=r"(a) : "l"(p));
    return a;
}
__device__ __forceinline__ void cp16(uint32_t dst, const void* src) {
    asm volatile("cp.async.cg.shared.global [%0], [%1], 16;" :: "r"(dst), "l"(src));
}
__device__ __forceinline__ void ldsm4(uint32_t* r, uint32_t a) {
    asm volatile("ldmatrix.sync.aligned.m8n8.x4.shared.b16 {%0,%1,%2,%3}, [%4];"
        : "=r"(r[0]), "=r"(r[1]), "=r"(r[2]), "=r"(r[3]) : "r"(a));
}
__device__ __forceinline__ void mma16816(float* c, const uint32_t* a,
                                         uint32_t b0, uint32_t b1) {
    asm volatile(
        "mma.sync.aligned.m16n8k16.row.col.f32.f16.f16.f32 "
        "{%0,%1,%2,%3}, {%4,%5,%6,%7}, {%8,%9}, {%0,%1,%2,%3};"
        : "+f"(c[0]), "+f"(c[1]), "+f"(c[2]), "+f"(c[3])
        : "r"(a[0]), "r"(a[1]), "r"(a[2]), "r"(a[3]), "r"(b0), "r"(b1));
}

// Tile rows are 64B (32 fp16); 16B chunk index XOR-swizzled with (row>>1)&3.
__device__ __forceinline__ uint32_t ldsm_addr(uint32_t tilebase, int row0, int ks, int lane) {
    const int sub = lane >> 3;
    const int row = row0 + (lane & 7) + ((sub & 1) << 3);
    const int ck  = ks * 2 + (sub >> 1);
    const int swz = ck ^ ((row >> 1) & 3);
    return tilebase + row * 64 + swz * 16;
}

__device__ __forceinline__ void splitB(float a, __half& h, __half& l) {
    h = __float2half(a);
    l = __float2half(a - __half2float(h));
}

// ---------------------------------------------------------------------------
// Prep: all 3 weight transposes in one launch. W[k][n] -> Wt_hi[n][k], Wt_lo[n][k]
// ---------------------------------------------------------------------------
__global__ __launch_bounds__(256)
void transpose_all_kernel(const float* __restrict__ W0, __half* __restrict__ T0h, __half* __restrict__ T0l,
                          const float* __restrict__ W1, __half* __restrict__ T1h, __half* __restrict__ T1l,
                          const float* __restrict__ W2, __half* __restrict__ T2h, __half* __restrict__ T2l)
{
    __shared__ float tile[32][33];
    const float* W = (blockIdx.z == 0) ? W0 : (blockIdx.z == 1) ? W1 : W2;
    __half* Th = (blockIdx.z == 0) ? T0h : (blockIdx.z == 1) ? T1h : T2h;
    __half* Tl = (blockIdx.z == 0) ? T0l : (blockIdx.z == 1) ? T1l : T2l;

    const int n0 = blockIdx.x * 32, k0 = blockIdx.y * 32;
    const int tx = threadIdx.x & 31, ty = threadIdx.x >> 5;   // 32 x 8
    #pragma unroll
    for (int i = 0; i < 4; ++i)
        tile[ty + i * 8][tx] = W[(size_t)(k0 + ty + i * 8) * HH + n0 + tx];
    __syncthreads();
    #pragma unroll
    for (int i = 0; i < 4; ++i) {
        const float v = tile[tx][ty + i * 8];
        __half h, l; splitB(v, h, l);
        Th[(size_t)(n0 + ty + i * 8) * HH + k0 + tx] = h;
        Tl[(size_t)(n0 + ty + i * 8) * HH + k0 + tx] = l;
    }
}

// ---------------------------------------------------------------------------
// Fused: x -> fp16 + windowed speaker-weighted msg -> fp16. One row/block.
// ---------------------------------------------------------------------------
__global__ __launch_bounds__(256)
void split_msg_kernel(const float* __restrict__ x,
                      const float* __restrict__ qmask,
                      const int* __restrict__ dia_len,
                      const int* __restrict__ wp_p,
                      const int* __restrict__ wf_p,
                      __half* __restrict__ xh, __half* __restrict__ mh)
{
    __shared__ float s_w[64];
    __shared__ int   s_nw;

    const int row = blockIdx.x;
    const int b   = row >> 10;
    const int t   = row & (TT - 1);
    const int tid = threadIdx.x;

    const int wp = *wp_p;
    const int wf = *wf_p;
    const int nw = wp + wf + 1;
    if (tid == 0) s_nw = nw;
    const int L = dia_len[b];

    if (tid < nw) {
        const int idx = t + tid - wp;
        float w = 0.f;
        if (idx >= 0 && idx <= L - 1) {
            const float* qt = qmask + ((size_t)row << 1);
            const float* qn = qmask + (((size_t)(b * TT + idx)) << 1);
            const int sp_t = qt[1] > qt[0];
            const int sp_n = qn[1] > qn[0];
            w = (sp_t == sp_n) ? 1.0f : 0.5f;
        }
        s_w[tid] = w;
    }
    __syncthreads();

    float cnt = 0.f;
    const int nw_s = s_nw;
    for (int o = 0; o < nw_s; ++o) cnt += (s_w[o] > 0.f) ? 1.f : 0.f;
    cnt = fmaxf(cnt, 1.f);
    const float inv = 1.f / cnt;

    // x row -> fp16
    {
        const size_t i = (size_t)row * HH + tid * 4;
        const float4 v = *(const float4*)(x + i);
        __half2 h0 = __floats2half2_rn(v.x, v.y);
        __half2 h1 = __floats2half2_rn(v.z, v.w);
        *(__half2*)(xh + i)     = h0;
        *(__half2*)(xh + i + 2) = h1;
    }

    // msg row
    float4 acc = make_float4(0.f, 0.f, 0.f, 0.f);
    const float4* x4 = (const float4*)x;
    for (int o = 0; o < nw_s; ++o) {
        const float w = s_w[o];
        if (w != 0.f) {
            const int idx = t + o - wp;
            const float4 v = x4[((size_t)(b * TT + idx)) * (HH / 4) + tid];
            acc.x += w * v.x; acc.y += w * v.y;
            acc.z += w * v.z; acc.w += w * v.w;
        }
    }
    acc.x *= inv; acc.y *= inv; acc.z *= inv; acc.w *= inv;

    const size_t base = (size_t)row * HH + tid * 4;
    *(__half2*)(mh + base)     = __floats2half2_rn(acc.x, acc.y);
    *(__half2*)(mh + base + 2) = __floats2half2_rn(acc.z, acc.w);
}

// ---------------------------------------------------------------------------
// HMMA GEMM, 4-stage cp.async, CTA 256x128, 16 warps (64x32 each), 512 thr.
// D = sum_g A@(Bh+Bl)   (A single fp16; B split hi/lo fp16)
// mode 0: h = D + b0 + b1; out = nv ? h : x; relu -> out_h (fp16)
// mode 1: z = x + D + b0 -> out_f (fp32)
// ---------------------------------------------------------------------------
__device__ __forceinline__ void load_tile_ca(uint32_t dstbase,
                                             const __half* __restrict__ src,
                                             int r0, int k0, int tid, int niter)
{
    #pragma unroll
    for (int j = 0; j < 2; ++j) {
        if (j >= niter) break;
        const int cc  = j * GTH + tid;
        const int row = cc >> 2;
        const int ck  = cc & 3;
        const int swz = ck ^ ((row >> 1) & 3);
        cp16(dstbase + row * 64 + swz * 16,
             src + (size_t)(r0 + row) * HH + k0 + ck * 8);
    }
}

__global__ __launch_bounds__(GTH, 1)
void hmma_gemm_kernel(const __half* __restrict__ A0,
                      const __half* __restrict__ Bh0, const __half* __restrict__ Bl0,
                      const __half* __restrict__ A1,
                      const __half* __restrict__ Bh1, const __half* __restrict__ Bl1,
                      int ngroups,
                      const float* __restrict__ b0v, const float* __restrict__ b1v,
                      const float* __restrict__ x, const int* __restrict__ dia_len,
                      int mode,
                      __half* __restrict__ out_h,
                      float* __restrict__ out_f)
{
    extern __shared__ char smem[];
    const uint32_t sbase = smem_u32(smem);
    const int tid  = threadIdx.x;
    const int wid  = tid >> 5, lane = tid & 31;
    const int warp_m = wid >> 2;     // 4 groups along M (64 rows each)
    const int warp_n = wid & 3;      // 4 groups along N (32 cols each)
    const int n0 = blockIdx.x * BN;
    const int m0 = blockIdx.y * BM;

    float acc[4][4][4];
    #pragma unroll
    for (int i = 0; i < 4; ++i)
        #pragma unroll
        for (int j = 0; j < 4; ++j)
            #pragma unroll
            for (int k = 0; k < 4; ++k) acc[i][j][k] = 0.f;

    const int NC = ngroups * (HH / BKE);

    auto do_load = [&](int cc, int stage) {
        const __half* A  = (cc < 32) ? A0  : A1;
        const __half* Bh = (cc < 32) ? Bh0 : Bh1;
        const __half* Bl = (cc < 32) ? Bl0 : Bl1;
        const int k0 = (cc & 31) * BKE;
        const uint32_t sb = sbase + stage * STAGE_BYTES;
        load_tile_ca(sb,         A,  m0, k0, tid, 2);   // 256x32 = 16KB
        load_tile_ca(sb + 16384, Bh, n0, k0, tid, 1);   // 128x32 = 8KB
        load_tile_ca(sb + 24576, Bl, n0, k0, tid, 1);
        asm volatile("cp.async.commit_group;" ::: "memory");
    };

    // prologue: fill NSTAGE-1 stages
    do_load(0, 0);
    do_load(1, 1);
    do_load(2, 2);

    int stage = 0;
    int nstage = 3;
    for (int c = 0; c < NC; ++c) {
        const int rem = NC - 1 - c;
        if (rem >= 2)      { asm volatile("cp.async.wait_group 2;" ::: "memory"); }
        else if (rem == 1) { asm volatile("cp.async.wait_group 1;" ::: "memory"); }
        else               { asm volatile("cp.async.wait_group 0;" ::: "memory"); }
        __syncthreads();

        if (c + 3 < NC) do_load(c + 3, nstage);

        const uint32_t sb  = sbase + stage * STAGE_BYTES;
        const uint32_t sA = sb, sBh = sb + 16384, sBl = sb + 24576;

        #pragma unroll
        for (int ks = 0; ks < 2; ++ks) {
            uint32_t af[4][4];
            #pragma unroll
            for (int mf = 0; mf < 4; ++mf)
                ldsm4(af[mf], ldsm_addr(sA, warp_m * 64 + mf * 16, ks, lane));
            #pragma unroll
            for (int nb = 0; nb < 2; ++nb) {
                uint32_t bh[4], bl[4];
                ldsm4(bh, ldsm_addr(sBh, warp_n * 32 + nb * 16, ks, lane));
                ldsm4(bl, ldsm_addr(sBl, warp_n * 32 + nb * 16, ks, lane));
                #pragma unroll
                for (int mf = 0; mf < 4; ++mf) {
                    float* c0 = acc[mf][nb * 2];
                    float* c1 = acc[mf][nb * 2 + 1];
                    mma16816(c0, af[mf], bh[0], bh[2]);
                    mma16816(c1, af[mf], bh[1], bh[3]);
                    mma16816(c0, af[mf], bl[0], bl[2]);
                    mma16816(c1, af[mf], bl[1], bl[3]);
                }
            }
        }
        stage = (stage == NSTAGE - 1) ? 0 : stage + 1;
        nstage = (nstage == NSTAGE - 1) ? 0 : nstage + 1;
    }

    // ---- epilogue ----
    const int groupID = lane >> 2;
    const int qc = (lane & 3) * 2;

    float2 biasv[4];
    #pragma unroll
    for (int nf = 0; nf < 4; ++nf) {
        const int col = n0 + warp_n * 32 + nf * 8 + qc;
        if (mode == 0) {
            biasv[nf].x = __ldg(b0v + col)     + __ldg(b1v + col);
            biasv[nf].y = __ldg(b0v + col + 1) + __ldg(b1v + col + 1);
        } else {
            biasv[nf].x = __ldg(b0v + col);
            biasv[nf].y = __ldg(b0v + col + 1);
        }
    }

    #pragma unroll
    for (int mf = 0; mf < 4; ++mf) {
        #pragma unroll
        for (int half = 0; half < 2; ++half) {
            const int m = m0 + warp_m * 64 + mf * 16 + groupID + half * 8;
            const size_t rb = (size_t)m * HH;
            const bool nv = (mode == 0) ? ((m & (TT - 1)) < dia_len[m >> 10]) : true;
            #pragma unroll
            for (int nf = 0; nf < 4; ++nf) {
                const int col = n0 + warp_n * 32 + nf * 8 + qc;
                float v0 = acc[mf][nf][half * 2 + 0] + biasv[nf].x;
                float v1 = acc[mf][nf][half * 2 + 1] + biasv[nf].y;
                if (mode == 0) {
                    if (!nv) {
                        const float2 xv = *(const float2*)(x + rb + col);
                        v0 = xv.x; v1 = xv.y;
                    }
                    v0 = fmaxf(v0, 0.f); v1 = fmaxf(v1, 0.f);
                    *(__half2*)(out_h + rb + col) = __floats2half2_rn(v0, v1);
                } else {
                    const float2 xv = *(const float2*)(x + rb + col);
                    float2 o; o.x = xv.x + v0; o.y = xv.y + v1;
                    *(float2*)(out_f + rb + col) = o;
                }
            }
        }
    }
}

// ---------------------------------------------------------------------------
// LayerNorm
// ---------------------------------------------------------------------------
__global__ __launch_bounds__(256)
void ln_kernel(const float* __restrict__ z,
               const float* __restrict__ gamma,
               const float* __restrict__ beta,
               float* __restrict__ out)
{
    __shared__ float sh_s[8], sh_ss[8];
    __shared__ float sh_mean, sh_inv;

    const int row = blockIdx.x;
    const int tid = threadIdx.x;
    const float4 v = ((const float4*)z)[(size_t)row * (HH / 4) + tid];

    float s  = v.x + v.y + v.z + v.w;
    float ss = v.x * v.x + v.y * v.y + v.z * v.z + v.w * v.w;
    #pragma unroll
    for (int off = 16; off; off >>= 1) {
        s  += __shfl_xor_sync(0xFFFFFFFFu, s,  off);
        ss += __shfl_xor_sync(0xFFFFFFFFu, ss, off);
    }
    const int wid = tid >> 5, lane = tid & 31;
    if (lane == 0) { sh_s[wid] = s; sh_ss[wid] = ss; }
    __syncthreads();
    if (tid == 0) {
        float ts = 0.f, tss = 0.f;
        #pragma unroll
        for (int w = 0; w < 8; ++w) { ts += sh_s[w]; tss += sh_ss[w]; }
        const float mean = ts * (1.f / HH);
        const float var  = tss * (1.f / HH) - mean * mean;
        sh_mean = mean;
        sh_inv  = rsqrtf(var + LN_EPS);
    }
    __syncthreads();
    const float mean = sh_mean, inv = sh_inv;

    const float4 g  = ((const float4*)gamma)[tid];
    const float4 bt = ((const float4*)beta)[tid];
    float4 o;
    o.x = g.x * (v.x - mean) * inv + bt.x;
    o.y = g.y * (v.y - mean) * inv + bt.y;
    o.z = g.z * (v.z - mean) * inv + bt.z;
    o.w = g.w * (v.w - mean) * inv + bt.w;
    ((float4*)out)[(size_t)row * (HH / 4) + tid] = o;
}

// ---------------------------------------------------------------------------
// Launch
// ---------------------------------------------------------------------------
extern "C" void kernel_launch(void* const* d_in, const int* in_sizes, int n_in,
                              void* d_out, int out_size)
{
    const float* x      = (const float*)d_in[0];
    const float* qmask  = (const float*)d_in[1];
    const int*   dia    = (const int*)  d_in[2];
    const int*   wp     = (const int*)  d_in[3];
    const int*   wf     = (const int*)  d_in[4];
    const float* W_msg  = (const float*)d_in[5];
    const float* b_msg  = (const float*)d_in[6];
    const float* W_self = (const float*)d_in[7];
    const float* b_self = (const float*)d_in[8];
    const float* W_out  = (const float*)d_in[9];
    const float* b_out  = (const float*)d_in[10];
    const float* gamma  = (const float*)d_in[11];
    const float* beta   = (const float*)d_in[12];
    float* out = (float*)d_out;

    __half *xh, *mh, *rh;
    __half *wsh, *wsl, *wmh, *wml, *woh, *wol;
    float* z;
    cudaGetSymbolAddress((void**)&xh, g_xh);
    cudaGetSymbolAddress((void**)&mh, g_mh);
    cudaGetSymbolAddress((void**)&rh, g_rh);
    cudaGetSymbolAddress((void**)&wsh, g_wst_h); cudaGetSymbolAddress((void**)&wsl, g_wst_l);
    cudaGetSymbolAddress((void**)&wmh, g_wmt_h); cudaGetSymbolAddress((void**)&wml, g_wmt_l);
    cudaGetSymbolAddress((void**)&woh, g_wot_h); cudaGetSymbolAddress((void**)&wol, g_wot_l);
    cudaGetSymbolAddress((void**)&z, g_z);

    cudaFuncSetAttribute(hmma_gemm_kernel,
                         cudaFuncAttributeMaxDynamicSharedMemorySize, GEMM_SMEM);

    // prep
    dim3 tgrid(HH / 32, HH / 32, 3);
    transpose_all_kernel<<<tgrid, 256>>>(W_self, wsh, wsl, W_msg, wmh, wml, W_out, woh, wol);
    split_msg_kernel<<<MM, 256>>>(x, qmask, dia, wp, wf, xh, mh);

    dim3 ggrid(HH / BN, MM / BM);   // (8, 32)
    // GEMM1: x@W_self + msg@W_msg -> relu/select -> r (fp16)
    hmma_gemm_kernel<<<ggrid, GTH, GEMM_SMEM>>>(
        xh, wsh, wsl, mh, wmh, wml, 2,
        b_self, b_msg, x, dia, 0, rh, nullptr);
    // GEMM2: r@W_out + b_out + x -> z (fp32)
    hmma_gemm_kernel<<<ggrid, GTH, GEMM_SMEM>>>(
        rh, woh, wol, nullptr, nullptr, nullptr, 1,
        b_out, nullptr, x, dia, 1, nullptr, z);

    ln_kernel<<<MM, 256>>>(z, gamma, beta, out);
}

// round 8
// speedup vs baseline: 2.5051x; 1.5391x over previous
#include <cuda_runtime.h>
#include <cuda_fp16.h>
#include <cstdint>

// Problem constants
#define BB 8
#define TT 1024
#define HH 1024
#define MM (BB * TT)      // 8192 rows
#define LN_EPS 1e-5f

// HMMA GEMM tiling: CTA 256x128, 16 warps of 64x32
#define BM 256
#define BN 128
#define BKE 32                 // fp16 K elems per stage
#define NSTAGE 4
#define STAGE_BYTES 24576      // A: 16KB, B: 8KB
#define GEMM_SMEM (NSTAGE * STAGE_BYTES)   // 98304
#define GTH 512

// ---------------------------------------------------------------------------
// Scratch (device globals — allocation-free rule)
// ---------------------------------------------------------------------------
__device__ __half g_xh[MM * HH];
__device__ __half g_mh[MM * HH];
__device__ __half g_rh[MM * HH];
__device__ __half g_wst[HH * HH];   // W_self^T [n][k]
__device__ __half g_wmt[HH * HH];   // W_msg^T
__device__ __half g_wot[HH * HH];   // W_out^T
__device__ float g_z[MM * HH];

// ---------------------------------------------------------------------------
// PTX helpers (baseline ISA — compiles at compute_103)
// ---------------------------------------------------------------------------
__device__ __forceinline__ uint32_t smem_u32(const void* p) {
    uint32_t a;
    asm("{ .reg .u64 t; cvta.to.shared.u64 t, %1; cvt.u32.u64 %0, t; }"
        : "=r"(a) : "l"(p));
    return a;
}
__device__ __forceinline__ void cp16(uint32_t dst, const void* src) {
    asm volatile("cp.async.cg.shared.global [%0], [%1], 16;" :: "r"(dst), "l"(src));
}
__device__ __forceinline__ void ldsm4(uint32_t* r, uint32_t a) {
    asm volatile("ldmatrix.sync.aligned.m8n8.x4.shared.b16 {%0,%1,%2,%3}, [%4];"
        : "=r"(r[0]), "=r"(r[1]), "=r"(r[2]), "=r"(r[3]) : "r"(a));
}
__device__ __forceinline__ void mma16816(float* c, const uint32_t* a,
                                         uint32_t b0, uint32_t b1) {
    asm volatile(
        "mma.sync.aligned.m16n8k16.row.col.f32.f16.f16.f32 "
        "{%0,%1,%2,%3}, {%4,%5,%6,%7}, {%8,%9}, {%0,%1,%2,%3};"
        : "+f"(c[0]), "+f"(c[1]), "+f"(c[2]), "+f"(c[3])
        : "r"(a[0]), "r"(a[1]), "r"(a[2]), "r"(a[3]), "r"(b0), "r"(b1));
}

// Tile rows are 64B (32 fp16); 16B chunk index XOR-swizzled with (row>>1)&3.
__device__ __forceinline__ uint32_t ldsm_addr(uint32_t tilebase, int row0, int ks, int lane) {
    const int sub = lane >> 3;
    const int row = row0 + (lane & 7) + ((sub & 1) << 3);
    const int ck  = ks * 2 + (sub >> 1);
    const int swz = ck ^ ((row >> 1) & 3);
    return tilebase + row * 64 + swz * 16;
}

// ---------------------------------------------------------------------------
// Prep: all 3 weight transposes in one launch. W[k][n] -> Wt[n][k] (fp16)
// ---------------------------------------------------------------------------
__global__ __launch_bounds__(256)
void transpose_all_kernel(const float* __restrict__ W0, __half* __restrict__ T0,
                          const float* __restrict__ W1, __half* __restrict__ T1,
                          const float* __restrict__ W2, __half* __restrict__ T2)
{
    __shared__ float tile[32][33];
    const float* W = (blockIdx.z == 0) ? W0 : (blockIdx.z == 1) ? W1 : W2;
    __half* Th = (blockIdx.z == 0) ? T0 : (blockIdx.z == 1) ? T1 : T2;

    const int n0 = blockIdx.x * 32, k0 = blockIdx.y * 32;
    const int tx = threadIdx.x & 31, ty = threadIdx.x >> 5;   // 32 x 8
    #pragma unroll
    for (int i = 0; i < 4; ++i)
        tile[ty + i * 8][tx] = W[(size_t)(k0 + ty + i * 8) * HH + n0 + tx];
    __syncthreads();
    #pragma unroll
    for (int i = 0; i < 4; ++i) {
        const float v = tile[tx][ty + i * 8];
        Th[(size_t)(n0 + ty + i * 8) * HH + k0 + tx] = __float2half(v);
    }
}

// ---------------------------------------------------------------------------
// Fused: x -> fp16 + windowed speaker-weighted msg -> fp16. One row/block.
// ---------------------------------------------------------------------------
__global__ __launch_bounds__(256)
void split_msg_kernel(const float* __restrict__ x,
                      const float* __restrict__ qmask,
                      const int* __restrict__ dia_len,
                      const int* __restrict__ wp_p,
                      const int* __restrict__ wf_p,
                      __half* __restrict__ xh, __half* __restrict__ mh)
{
    __shared__ float s_w[64];
    __shared__ int   s_nw;

    const int row = blockIdx.x;
    const int b   = row >> 10;
    const int t   = row & (TT - 1);
    const int tid = threadIdx.x;

    const int wp = *wp_p;
    const int wf = *wf_p;
    const int nw = wp + wf + 1;
    if (tid == 0) s_nw = nw;
    const int L = dia_len[b];

    if (tid < nw) {
        const int idx = t + tid - wp;
        float w = 0.f;
        if (idx >= 0 && idx <= L - 1) {
            const float* qt = qmask + ((size_t)row << 1);
            const float* qn = qmask + (((size_t)(b * TT + idx)) << 1);
            const int sp_t = qt[1] > qt[0];
            const int sp_n = qn[1] > qn[0];
            w = (sp_t == sp_n) ? 1.0f : 0.5f;
        }
        s_w[tid] = w;
    }
    __syncthreads();

    float cnt = 0.f;
    const int nw_s = s_nw;
    for (int o = 0; o < nw_s; ++o) cnt += (s_w[o] > 0.f) ? 1.f : 0.f;
    cnt = fmaxf(cnt, 1.f);
    const float inv = 1.f / cnt;

    // x row -> fp16
    {
        const size_t i = (size_t)row * HH + tid * 4;
        const float4 v = *(const float4*)(x + i);
        *(__half2*)(xh + i)     = __floats2half2_rn(v.x, v.y);
        *(__half2*)(xh + i + 2) = __floats2half2_rn(v.z, v.w);
    }

    // msg row
    float4 acc = make_float4(0.f, 0.f, 0.f, 0.f);
    const float4* x4 = (const float4*)x;
    for (int o = 0; o < nw_s; ++o) {
        const float w = s_w[o];
        if (w != 0.f) {
            const int idx = t + o - wp;
            const float4 v = x4[((size_t)(b * TT + idx)) * (HH / 4) + tid];
            acc.x += w * v.x; acc.y += w * v.y;
            acc.z += w * v.z; acc.w += w * v.w;
        }
    }
    acc.x *= inv; acc.y *= inv; acc.z *= inv; acc.w *= inv;

    const size_t base = (size_t)row * HH + tid * 4;
    *(__half2*)(mh + base)     = __floats2half2_rn(acc.x, acc.y);
    *(__half2*)(mh + base + 2) = __floats2half2_rn(acc.z, acc.w);
}

// ---------------------------------------------------------------------------
// HMMA GEMM, 4-stage cp.async, CTA 256x128, 16 warps (64x32 each), 512 thr.
// D = sum_g A_g @ B_g^T   (single fp16 operands)
// mode 0: h = D + b0 + b1; out = nv ? h : x; relu -> out_h (fp16)
// mode 1: z = x + D + b0 -> out_f (fp32)
// ---------------------------------------------------------------------------
__device__ __forceinline__ void load_tile_ca(uint32_t dstbase,
                                             const __half* __restrict__ src,
                                             int r0, int k0, int tid, int niter)
{
    #pragma unroll
    for (int j = 0; j < 2; ++j) {
        if (j >= niter) break;
        const int cc  = j * GTH + tid;
        const int row = cc >> 2;
        const int ck  = cc & 3;
        const int swz = ck ^ ((row >> 1) & 3);
        cp16(dstbase + row * 64 + swz * 16,
             src + (size_t)(r0 + row) * HH + k0 + ck * 8);
    }
}

__global__ __launch_bounds__(GTH, 1)
void hmma_gemm_kernel(const __half* __restrict__ A0, const __half* __restrict__ B0,
                      const __half* __restrict__ A1, const __half* __restrict__ B1,
                      int ngroups,
                      const float* __restrict__ b0v, const float* __restrict__ b1v,
                      const float* __restrict__ x, const int* __restrict__ dia_len,
                      int mode,
                      __half* __restrict__ out_h,
                      float* __restrict__ out_f)
{
    extern __shared__ char smem[];
    const uint32_t sbase = smem_u32(smem);
    const int tid  = threadIdx.x;
    const int wid  = tid >> 5, lane = tid & 31;
    const int warp_m = wid >> 2;     // 4 groups along M (64 rows each)
    const int warp_n = wid & 3;      // 4 groups along N (32 cols each)
    const int n0 = blockIdx.x * BN;
    const int m0 = blockIdx.y * BM;

    float acc[4][4][4];
    #pragma unroll
    for (int i = 0; i < 4; ++i)
        #pragma unroll
        for (int j = 0; j < 4; ++j)
            #pragma unroll
            for (int k = 0; k < 4; ++k) acc[i][j][k] = 0.f;

    const int NC = ngroups * (HH / BKE);

    auto do_load = [&](int cc, int stage) {
        const __half* A = (cc < 32) ? A0 : A1;
        const __half* B = (cc < 32) ? B0 : B1;
        const int k0 = (cc & 31) * BKE;
        const uint32_t sb = sbase + stage * STAGE_BYTES;
        load_tile_ca(sb,         A, m0, k0, tid, 2);   // 256x32 = 16KB
        load_tile_ca(sb + 16384, B, n0, k0, tid, 1);   // 128x32 = 8KB
        asm volatile("cp.async.commit_group;" ::: "memory");
    };

    // prologue: fill NSTAGE-1 stages
    do_load(0, 0);
    do_load(1, 1);
    do_load(2, 2);

    int stage = 0;
    int nstage = 3;
    for (int c = 0; c < NC; ++c) {
        const int rem = NC - 1 - c;
        if (rem >= 2)      { asm volatile("cp.async.wait_group 2;" ::: "memory"); }
        else if (rem == 1) { asm volatile("cp.async.wait_group 1;" ::: "memory"); }
        else               { asm volatile("cp.async.wait_group 0;" ::: "memory"); }
        __syncthreads();

        if (c + 3 < NC) do_load(c + 3, nstage);

        const uint32_t sb = sbase + stage * STAGE_BYTES;
        const uint32_t sA = sb, sB = sb + 16384;

        #pragma unroll
        for (int ks = 0; ks < 2; ++ks) {
            uint32_t af[4][4];
            #pragma unroll
            for (int mf = 0; mf < 4; ++mf)
                ldsm4(af[mf], ldsm_addr(sA, warp_m * 64 + mf * 16, ks, lane));
            #pragma unroll
            for (int nb = 0; nb < 2; ++nb) {
                uint32_t bf[4];
                ldsm4(bf, ldsm_addr(sB, warp_n * 32 + nb * 16, ks, lane));
                #pragma unroll
                for (int mf = 0; mf < 4; ++mf) {
                    mma16816(acc[mf][nb * 2],     af[mf], bf[0], bf[2]);
                    mma16816(acc[mf][nb * 2 + 1], af[mf], bf[1], bf[3]);
                }
            }
        }
        stage = (stage == NSTAGE - 1) ? 0 : stage + 1;
        nstage = (nstage == NSTAGE - 1) ? 0 : nstage + 1;
    }

    // ---- epilogue ----
    const int groupID = lane >> 2;
    const int qc = (lane & 3) * 2;

    float2 biasv[4];
    #pragma unroll
    for (int nf = 0; nf < 4; ++nf) {
        const int col = n0 + warp_n * 32 + nf * 8 + qc;
        if (mode == 0) {
            biasv[nf].x = __ldg(b0v + col)     + __ldg(b1v + col);
            biasv[nf].y = __ldg(b0v + col + 1) + __ldg(b1v + col + 1);
        } else {
            biasv[nf].x = __ldg(b0v + col);
            biasv[nf].y = __ldg(b0v + col + 1);
        }
    }

    #pragma unroll
    for (int mf = 0; mf < 4; ++mf) {
        #pragma unroll
        for (int half = 0; half < 2; ++half) {
            const int m = m0 + warp_m * 64 + mf * 16 + groupID + half * 8;
            const size_t rb = (size_t)m * HH;
            const bool nv = (mode == 0) ? ((m & (TT - 1)) < dia_len[m >> 10]) : true;
            #pragma unroll
            for (int nf = 0; nf < 4; ++nf) {
                const int col = n0 + warp_n * 32 + nf * 8 + qc;
                float v0 = acc[mf][nf][half * 2 + 0] + biasv[nf].x;
                float v1 = acc[mf][nf][half * 2 + 1] + biasv[nf].y;
                if (mode == 0) {
                    if (!nv) {
                        const float2 xv = *(const float2*)(x + rb + col);
                        v0 = xv.x; v1 = xv.y;
                    }
                    v0 = fmaxf(v0, 0.f); v1 = fmaxf(v1, 0.f);
                    *(__half2*)(out_h + rb + col) = __floats2half2_rn(v0, v1);
                } else {
                    const float2 xv = *(const float2*)(x + rb + col);
                    float2 o; o.x = xv.x + v0; o.y = xv.y + v1;
                    *(float2*)(out_f + rb + col) = o;
                }
            }
        }
    }
}

// ---------------------------------------------------------------------------
// LayerNorm
// ---------------------------------------------------------------------------
__global__ __launch_bounds__(256)
void ln_kernel(const float* __restrict__ z,
               const float* __restrict__ gamma,
               const float* __restrict__ beta,
               float* __restrict__ out)
{
    __shared__ float sh_s[8], sh_ss[8];
    __shared__ float sh_mean, sh_inv;

    const int row = blockIdx.x;
    const int tid = threadIdx.x;
    const float4 v = ((const float4*)z)[(size_t)row * (HH / 4) + tid];

    float s  = v.x + v.y + v.z + v.w;
    float ss = v.x * v.x + v.y * v.y + v.z * v.z + v.w * v.w;
    #pragma unroll
    for (int off = 16; off; off >>= 1) {
        s  += __shfl_xor_sync(0xFFFFFFFFu, s,  off);
        ss += __shfl_xor_sync(0xFFFFFFFFu, ss, off);
    }
    const int wid = tid >> 5, lane = tid & 31;
    if (lane == 0) { sh_s[wid] = s; sh_ss[wid] = ss; }
    __syncthreads();
    if (tid == 0) {
        float ts = 0.f, tss = 0.f;
        #pragma unroll
        for (int w = 0; w < 8; ++w) { ts += sh_s[w]; tss += sh_ss[w]; }
        const float mean = ts * (1.f / HH);
        const float var  = tss * (1.f / HH) - mean * mean;
        sh_mean = mean;
        sh_inv  = rsqrtf(var + LN_EPS);
    }
    __syncthreads();
    const float mean = sh_mean, inv = sh_inv;

    const float4 g  = ((const float4*)gamma)[tid];
    const float4 bt = ((const float4*)beta)[tid];
    float4 o;
    o.x = g.x * (v.x - mean) * inv + bt.x;
    o.y = g.y * (v.y - mean) * inv + bt.y;
    o.z = g.z * (v.z - mean) * inv + bt.z;
    o.w = g.w * (v.w - mean) * inv + bt.w;
    ((float4*)out)[(size_t)row * (HH / 4) + tid] = o;
}

// ---------------------------------------------------------------------------
// Launch
// ---------------------------------------------------------------------------
extern "C" void kernel_launch(void* const* d_in, const int* in_sizes, int n_in,
                              void* d_out, int out_size)
{
    const float* x      = (const float*)d_in[0];
    const float* qmask  = (const float*)d_in[1];
    const int*   dia    = (const int*)  d_in[2];
    const int*   wp     = (const int*)  d_in[3];
    const int*   wf     = (const int*)  d_in[4];
    const float* W_msg  = (const float*)d_in[5];
    const float* b_msg  = (const float*)d_in[6];
    const float* W_self = (const float*)d_in[7];
    const float* b_self = (const float*)d_in[8];
    const float* W_out  = (const float*)d_in[9];
    const float* b_out  = (const float*)d_in[10];
    const float* gamma  = (const float*)d_in[11];
    const float* beta   = (const float*)d_in[12];
    float* out = (float*)d_out;

    __half *xh, *mh, *rh, *wst, *wmt, *wot;
    float* z;
    cudaGetSymbolAddress((void**)&xh, g_xh);
    cudaGetSymbolAddress((void**)&mh, g_mh);
    cudaGetSymbolAddress((void**)&rh, g_rh);
    cudaGetSymbolAddress((void**)&wst, g_wst);
    cudaGetSymbolAddress((void**)&wmt, g_wmt);
    cudaGetSymbolAddress((void**)&wot, g_wot);
    cudaGetSymbolAddress((void**)&z, g_z);

    cudaFuncSetAttribute(hmma_gemm_kernel,
                         cudaFuncAttributeMaxDynamicSharedMemorySize, GEMM_SMEM);

    // prep
    dim3 tgrid(HH / 32, HH / 32, 3);
    transpose_all_kernel<<<tgrid, 256>>>(W_self, wst, W_msg, wmt, W_out, wot);
    split_msg_kernel<<<MM, 256>>>(x, qmask, dia, wp, wf, xh, mh);

    dim3 ggrid(HH / BN, MM / BM);   // (8, 32)
    // GEMM1: x@W_self + msg@W_msg -> relu/select -> r (fp16)
    hmma_gemm_kernel<<<ggrid, GTH, GEMM_SMEM>>>(
        xh, wst, mh, wmt, 2,
        b_self, b_msg, x, dia, 0, rh, nullptr);
    // GEMM2: r@W_out + b_out + x -> z (fp32)
    hmma_gemm_kernel<<<ggrid, GTH, GEMM_SMEM>>>(
        rh, wot, nullptr, nullptr, 1,
        b_out, nullptr, x, dia, 1, nullptr, z);

    ln_kernel<<<MM, 256>>>(z, gamma, beta, out);
}